// round 16
// baseline (speedup 1.0000x reference)
#include <cuda_runtime.h>
#include <cstdint>

#define TLEN   1024
#define BATCH  64
#define NW     8                 // warps per block
#define NTH    (NW * 32)         // 256 threads
#define RPT    4                 // rows per thread (NTH*RPT == TLEN)
#define NPAIR  512               // column pairs (2 cols per warp-step)
#define WSTEP  (NPAIR + 31)      // 543 warp steps
#define RING   128               // ring entries per warp boundary (pow2)
#define PUB    8                 // publish granularity (pairs)
#define INFV   1e30f

__device__ float g_losses[BATCH];
__device__ unsigned int g_done = 0;   // self-resetting ticket (wraps at BATCH)

__device__ __forceinline__ float sqrt_approx(float x) {
    float r; asm("sqrt.approx.f32 %0, %1;" : "=f"(r) : "f"(x)); return r;
}
__device__ __forceinline__ void membar_cta() {
    asm volatile("membar.cta;" ::: "memory");
}

// One block per batch, NO block-wide barriers in the main loop.
// Warp w owns rows [w*128, w*128+128); lane l owns rows w*128+l*4 .. +3.
// At warp-step s, lane l processes column pair k = s - l (cols 2k, 2k+1) as a
// 4x2 register tile. Boundary row (C,L @ c0,c1) flows:
//   lane l-1 -> lane l : __shfl_up of last step's bottom quad (exact lockstep)
//   warp w -> warp w+1 : smem ring + progress counter, membar.cta ordered,
//                        published every PUB pairs, ring back-pressured.
// EVERY warp (incl. the last) publishes prog[w] — the last warp's publication
// exists solely to satisfy upstream back-pressure (fixes the R11 deadlock).
// DP carried:
//   C[i,j] = D(i,j) + min(diag, up, left)
//   L[i,j] = L1w(i,j) + L[parent], parent = first-min in order (diag, up,
// left) == reference backtrace rule, so loss = L[T-1,T-1] (no backtrace).
__global__ void __launch_bounds__(NTH, 1)
dtw_kernel(const float* __restrict__ preds, const float* __restrict__ targs,
           const float* __restrict__ subcoef, float* __restrict__ out)
{
    __shared__ float4 qs[NPAIR];             // (qx0,qy0,qx1,qy1) per pair
    __shared__ float4 ring[NW - 1][RING];    // warp w -> w+1 boundary entries
    __shared__ int    prog[NW];              // last pair completed by warp w

    const int b = blockIdx.x;
    const int t = threadIdx.x;
    const int w = t >> 5;
    const int l = t & 31;

    const float* P = preds + (size_t)b * TLEN * 4;
    const float* Q = targs + (size_t)b * TLEN * 4;

    for (int k = t; k < NPAIR; k += NTH) {
        float4 a = *(const float4*)(Q + 8 * k);
        float4 c = *(const float4*)(Q + 8 * k + 4);
        qs[k] = make_float4(a.x, a.y, c.x, c.y);
    }
    if (t < NW) prog[t] = -1;

    float px[RPT], py[RPT];
    const int rb = t * RPT;
#pragma unroll
    for (int r = 0; r < RPT; r++) {
        px[r] = P[(rb + r) * 4 + 0];
        py[r] = P[(rb + r) * 4 + 1];
    }
    const float sc0 = subcoef[0], sc1 = subcoef[1];

    float Cl[RPT], Ll[RPT];                  // own rows at col c-1
#pragma unroll
    for (int r = 0; r < RPT; r++) { Cl[r] = INFV; Ll[r] = 0.f; }
    float bCp = INFV, bLp = 0.f;             // neighbor bottom @ c0-1 (diag lag)
    float4 botPrev = make_float4(INFV, 0.f, INFV, 0.f);  // my bottom, last pair
    int cachedUp = -1;                       // lane 0: last seen prog[w-1]
    int cachedDn = -1;                       // lane 31: last seen prog[w+1]

    __syncthreads();                         // qs + prog init visible

    for (int s = 0; s < WSTEP; ++s) {
        // boundary from lane l-1 (last step's bottom quad) — all lanes, full mask
        float bqx = __shfl_up_sync(0xffffffffu, botPrev.x, 1);
        float bqy = __shfl_up_sync(0xffffffffu, botPrev.y, 1);
        float bqz = __shfl_up_sync(0xffffffffu, botPrev.z, 1);
        float bqw = __shfl_up_sync(0xffffffffu, botPrev.w, 1);

        const int k = s - l;
        if (k >= 0 && k < NPAIR) {
            float4 bv = make_float4(bqx, bqy, bqz, bqw);
            if (l == 0) {
                if (w == 0) {
                    bv = make_float4(INFV, 0.f, INFV, 0.f);   // top of matrix
                } else {
                    if (cachedUp < k) {                       // need newer data
                        int v;
                        do { v = *(volatile int*)&prog[w - 1];
                             if (v < k) __nanosleep(40);
                        } while (v < k);
                        cachedUp = v;
                        membar_cta();                         // acquire
                    }
                    bv = ring[w - 1][k & (RING - 1)];
                }
            }
            const float4 q = qs[k];
            const bool orig = (w == 0) && (l == 0) && (k == 0);

            float A[RPT], LA[RPT];                 // column c0 = 2k
            {
                float dg = bCp, dgl = bLp, up = bv.x, upl = bv.y;
#pragma unroll
                for (int r = 0; r < RPT; r++) {
                    const float dx = px[r] - q.x, dy = py[r] - q.y;
                    const float D  = sqrt_approx(fmaf(dx, dx, dy * dy));
                    const float m1  = fminf(dg, up);
                    const float m1l = (dg <= up) ? dgl : upl;
                    float m  = fminf(m1, Cl[r]);
                    float Lp = (m1 <= Cl[r]) ? m1l : Ll[r];
                    if (r == 0 && orig) { m = 0.f; Lp = 0.f; }   // C[0,0]=D[0,0]
                    A[r]  = D + m;
                    LA[r] = fmaf(fabsf(dx), sc0, fmaf(fabsf(dy), sc1, Lp));
                    dg = Cl[r]; dgl = Ll[r];
                    up = A[r];  upl = LA[r];
                }
            }
            float Bv[RPT], LB[RPT];                // column c1 = 2k+1
            {
                float dg = bv.x, dgl = bv.y, up = bv.z, upl = bv.w;
#pragma unroll
                for (int r = 0; r < RPT; r++) {
                    const float dx = px[r] - q.z, dy = py[r] - q.w;
                    const float D  = sqrt_approx(fmaf(dx, dx, dy * dy));
                    const float m1  = fminf(dg, up);
                    const float m1l = (dg <= up) ? dgl : upl;
                    const float m  = fminf(m1, A[r]);
                    const float Lp = (m1 <= A[r]) ? m1l : LA[r];
                    Bv[r] = D + m;
                    LB[r] = fmaf(fabsf(dx), sc0, fmaf(fabsf(dy), sc1, Lp));
                    dg = A[r];  dgl = LA[r];
                    up = Bv[r]; upl = LB[r];
                }
            }
#pragma unroll
            for (int r = 0; r < RPT; r++) { Cl[r] = Bv[r]; Ll[r] = LB[r]; }
            bCp = bv.z; bLp = bv.w;
            botPrev = make_float4(A[RPT-1], LA[RPT-1], Bv[RPT-1], LB[RPT-1]);

            if (l == 31) {
                if (w < NW - 1) {
                    // back-pressure: slot (k & 127) reusable once warp w+1's
                    // lane 31 completed pair k-RING (lane 0 consumed earlier).
                    if (cachedDn < k - RING) {
                        int v;
                        do { v = *(volatile int*)&prog[w + 1];
                             if (v < k - RING) __nanosleep(40);
                        } while (v < k - RING);
                        cachedDn = v;
                    }
                    ring[w][k & (RING - 1)] = botPrev;
                }
                // ALL warps publish progress (last warp's feeds back-pressure).
                if ((k & (PUB - 1)) == PUB - 1) {
                    if (w < NW - 1) membar_cta();              // release
                    *(volatile int*)&prog[w] = k;
                }
                if (w == NW - 1 && k == NPAIR - 1)
                    g_losses[b] = LB[RPT - 1];                 // cell (1023,1023)
            }
        }
    }

    // Warp 7 lane 31 wrote g_losses[b]; it also takes the block ticket.
    if (w == NW - 1 && l == 31) {
        __threadfence();
        unsigned int old = atomicInc(&g_done, BATCH - 1);      // wraps -> reset
        if (old == BATCH - 1) {
            __threadfence();
            float sum = 0.f;
#pragma unroll
            for (int i = 0; i < BATCH; i++) sum += __ldcg(&g_losses[i]);
            out[0] = sum;
        }
    }
}

extern "C" void kernel_launch(void* const* d_in, const int* in_sizes, int n_in,
                              void* d_out, int out_size)
{
    const float* preds   = (const float*)d_in[0];
    const float* targs   = (const float*)d_in[1];
    const float* subcoef = (const float*)d_in[2];
    float* out = (float*)d_out;
    (void)in_sizes; (void)n_in; (void)out_size;

    dtw_kernel<<<BATCH, NTH>>>(preds, targs, subcoef, out);
}

// round 17
// speedup vs baseline: 4.4307x; 4.4307x over previous
#include <cuda_runtime.h>

#define TLEN  1024
#define BATCH 64
#define NTH   256               // 8 warps = 2 per SMSP
#define RPT   4                 // rows per thread (NTH*RPT == TLEN)
#define NCG   256               // column groups of 4 cols (2 pairs) per step
#define NSTEP (NCG + NTH - 1)   // 511;  NCG == NTH -> full concurrent window
#define INFV  1e30f

__device__ float g_losses[BATCH];
__device__ unsigned int g_done = 0;   // self-resetting ticket (wraps at BATCH)

__device__ __forceinline__ float sqrt_approx(float x) {
    float r; asm("sqrt.approx.f32 %0, %1;" : "=f"(r) : "f"(x)); return r;
}

// One block per batch. Thread t owns rows 4t..4t+3. At step s it processes
// column group k = s - t (4 columns = 2 pairs): a 4x4 register tile.
// Cross-thread dep: bottom row of thread t-1 over those 4 columns,
// double-buffered in shared as 2 float4 planes (16B stride, conflict-free).
// NCG == NTH keeps the whole block concurrently active (the R8 mistake was
// NPG < NTH, which idled half the warps).
// DP carried:
//   C[i,j] = D(i,j) + min(diag, up, left)
//   L[i,j] = L1w(i,j) + L[parent], parent = first-min in order (diag, up,
// left) == reference backtrace rule, so loss = L[T-1,T-1] (no backtrace).
__global__ void __launch_bounds__(NTH, 1)
dtw_kernel(const float* __restrict__ preds, const float* __restrict__ targs,
           const float* __restrict__ subcoef, float* __restrict__ out)
{
    __shared__ float4 qs4[2][NCG];        // quad i of group g: cols 4g+2i, 4g+2i+1
    __shared__ float4 bnd[2][2][NTH + 1]; // [parity][pair][thread], ghost slot 0

    const int b = blockIdx.x;
    const int t = threadIdx.x;
    const float* P = preds + (size_t)b * TLEN * 4;
    const float* Q = targs + (size_t)b * TLEN * 4;

    for (int p = t; p < TLEN / 2; p += NTH) {      // pair p = cols 2p, 2p+1
        float4 a = *(const float4*)(Q + 8 * p);
        float4 c = *(const float4*)(Q + 8 * p + 4);
        qs4[p & 1][p >> 1] = make_float4(a.x, a.y, c.x, c.y);
    }
    float px[RPT], py[RPT];
    const int rb = t * RPT;
#pragma unroll
    for (int r = 0; r < RPT; r++) {
        px[r] = P[(rb + r) * 4 + 0];
        py[r] = P[(rb + r) * 4 + 1];
    }
    const float sc0 = subcoef[0], sc1 = subcoef[1];

    if (t == 0) {                          // constant top boundary (both parities)
        float4 inf4 = make_float4(INFV, 0.f, INFV, 0.f);
        bnd[0][0][0] = inf4; bnd[0][1][0] = inf4;
        bnd[1][0][0] = inf4; bnd[1][1][0] = inf4;
    }

    float Cl[RPT], Ll[RPT];                // own rows at col c-1
#pragma unroll
    for (int r = 0; r < RPT; r++) { Cl[r] = INFV; Ll[r] = 0.f; }
    float bCp = INFV, bLp = 0.f;           // t-1 bottom at first col - 1 (diag lag)

    __syncthreads();

    for (int s = 0; s < NSTEP; ++s) {
        const int k  = s - t;
        const int Pw = s & 1;
        if (k >= 0 && k < NCG) {
            const bool orig = (t == 0) && (k == 0);
            float dgC = bCp, dgL = bLp;

#pragma unroll
            for (int i = 0; i < 2; i++) {          // 2 column pairs
                const float4 bq = bnd[Pw ^ 1][i][t];   // t-1 bottom @ {c0, c1}
                const float4 q  = qs4[i][k];

                float A[RPT], LA[RPT];             // column c0 = 4k+2i
                {
                    float dg = dgC, dgl = dgL, up = bq.x, upl = bq.y;
#pragma unroll
                    for (int r = 0; r < RPT; r++) {
                        const float dx = px[r] - q.x, dy = py[r] - q.y;
                        const float D  = sqrt_approx(fmaf(dx, dx, dy * dy));
                        const float m1  = fminf(dg, up);
                        const float m1l = (dg <= up) ? dgl : upl;
                        float m  = fminf(m1, Cl[r]);
                        float Lp = (m1 <= Cl[r]) ? m1l : Ll[r];
                        if (i == 0 && r == 0 && orig) { m = 0.f; Lp = 0.f; }
                        A[r]  = D + m;
                        LA[r] = fmaf(fabsf(dx), sc0, fmaf(fabsf(dy), sc1, Lp));
                        dg = Cl[r]; dgl = Ll[r];
                        up = A[r];  upl = LA[r];
                    }
                }
                float Bv[RPT], LB[RPT];            // column c1 = 4k+2i+1
                {
                    float dg = bq.x, dgl = bq.y, up = bq.z, upl = bq.w;
#pragma unroll
                    for (int r = 0; r < RPT; r++) {
                        const float dx = px[r] - q.z, dy = py[r] - q.w;
                        const float D  = sqrt_approx(fmaf(dx, dx, dy * dy));
                        const float m1  = fminf(dg, up);
                        const float m1l = (dg <= up) ? dgl : upl;
                        const float m  = fminf(m1, A[r]);
                        const float Lp = (m1 <= A[r]) ? m1l : LA[r];
                        Bv[r] = D + m;
                        LB[r] = fmaf(fabsf(dx), sc0, fmaf(fabsf(dy), sc1, Lp));
                        dg = A[r];  dgl = LA[r];
                        up = Bv[r]; upl = LB[r];
                    }
                }
#pragma unroll
                for (int r = 0; r < RPT; r++) { Cl[r] = Bv[r]; Ll[r] = LB[r]; }
                dgC = bq.z; dgL = bq.w;            // diag for next pair's c0

                bnd[Pw][i][t + 1] =
                    make_float4(A[RPT-1], LA[RPT-1], Bv[RPT-1], LB[RPT-1]);

                if (t == NTH - 1 && k == NCG - 1 && i == 1)   // cell (1023,1023)
                    g_losses[b] = LB[RPT - 1];
            }
            bCp = dgC; bLp = dgL;                  // boundary diag lag across steps
        }
        __syncthreads();
    }

    // Last block sums all batch losses in fixed order (deterministic).
    if (t == NTH - 1) {
        __threadfence();
        unsigned int old = atomicInc(&g_done, BATCH - 1);  // wraps -> self-reset
        if (old == BATCH - 1) {
            __threadfence();
            float sum = 0.f;
#pragma unroll
            for (int i = 0; i < BATCH; i++) sum += __ldcg(&g_losses[i]);
            out[0] = sum;
        }
    }
}

extern "C" void kernel_launch(void* const* d_in, const int* in_sizes, int n_in,
                              void* d_out, int out_size)
{
    const float* preds   = (const float*)d_in[0];
    const float* targs   = (const float*)d_in[1];
    const float* subcoef = (const float*)d_in[2];
    float* out = (float*)d_out;
    (void)in_sizes; (void)n_in; (void)out_size;

    dtw_kernel<<<BATCH, NTH>>>(preds, targs, subcoef, out);
}